// round 11
// baseline (speedup 1.0000x reference)
#include <cuda_runtime.h>
#include <math.h>

// Problem constants
#define T_STEPS 16384
#define HID     1024
#define INP     256
#define NLAB    32

#define NCTA    64           // persistent CTAs
#define WPC     8            // warps per CTA (proven narrow-CTA shape)
#define TPB     (WPC * 32)   // 256
#define RPW     2            // rows per warp; NCTA*WPC*RPW == HID

// Hidden state words: fp32 h with mantissa LSB = 1-bit step tag
// tau(s) = (s>>1)&1. Double-buffered by parity s&1; stale content is from
// step s-2 whose tau differs -> LSB equality == ready. Naturally-aligned 4B
// accesses are single-copy atomic, so value+tag never tear; validity is
// in-word, so no fences anywhere. LSB clobber <= 2^-23 relative (absorbed by
// the contractive recurrence). Reset restores both buffers every launch.
__device__ unsigned g_hbuf[2][HID];

__device__ __forceinline__ uint4 ldv4(const unsigned* p) {
    uint4 v;
    asm volatile("ld.volatile.global.v4.u32 {%0,%1,%2,%3}, [%4];"
                 : "=r"(v.x), "=r"(v.y), "=r"(v.z), "=r"(v.w) : "l"(p));
    return v;
}
__device__ __forceinline__ void stx32(unsigned* p, unsigned v) {
    asm volatile("st.relaxed.gpu.global.u32 [%0], %1;" :: "l"(p), "r"(v) : "memory");
}
__device__ __forceinline__ float tanh_fast(float v) {
    float r;
    asm volatile("tanh.approx.f32 %0, %1;" : "=f"(r) : "f"(v));
    return r;
}
__device__ __forceinline__ unsigned notready(uint4 v, unsigned tau) {
    return ((v.x ^ tau) | (v.y ^ tau) | (v.z ^ tau) | (v.w ^ tau)) & 1u;
}

__global__ void rnn_reset_kernel() {
    int t = threadIdx.x;
    for (int i = t; i < HID; i += blockDim.x) {
        g_hbuf[0][i] = 0u;   // h0 = 0.0f, LSB 0 == tau(0): valid for step 0
        g_hbuf[1][i] = 1u;   // LSB 1 != tau(1)=0: step-1 consumers must wait
    }
}

__global__ void __launch_bounds__(TPB, 1) rnn_scan_kernel(
    const float* __restrict__ X,    // [T, 1, 256]
    const float* __restrict__ Wi,   // [1024, 256]
    const float* __restrict__ bi,   // [1024]
    const float* __restrict__ Wh,   // [1024, 1024]
    const float* __restrict__ bh,   // [1024]
    const float* __restrict__ Wo,   // [32, 1024]
    const float* __restrict__ bo,   // [32]
    float* __restrict__ out)        // [32] log-softmax
{
    const int t    = threadIdx.x;
    const int lane = t & 31;
    const int warp = t >> 5;
    const int r0   = blockIdx.x * (WPC * RPW) + 2 * warp;  // this warp's rows
    const int r1   = r0 + 1;

    // Double-buffered plain-float h staged per CTA. One barrier per step.
    __shared__ float sh[2][HID];

    // ---- Register-resident weights (held for all 16384 steps) ----
    // Lane l owns hidden columns (k/4)*128 + 4l + (k%4), k=0..31; one LDS.128
    // of h per group feeds BOTH rows' FMAs.
    float w0[32], w1[32];
    #pragma unroll
    for (int k = 0; k < 32; k++) {
        int col = (k >> 2) * 128 + 4 * lane + (k & 3);
        w0[k] = Wh[r0 * HID + col];
        w1[k] = Wh[r1 * HID + col];
    }
    float wi0[8], wi1[8];
    #pragma unroll
    for (int k = 0; k < 8; k++) {
        int col = (k >> 2) * 128 + 4 * lane + (k & 3);
        wi0[k] = Wi[r0 * INP + col];
        wi1[k] = Wi[r1 * INP + col];
    }
    const float bias0 = bi[r0] + bh[r0];
    const float bias1 = bi[r1] + bh[r1];

    // ---- 3-deep input pipeline: x0 = step s, x1 = step s+1 ----
    const float4* X4 = (const float4*)X;   // step s slice at X4[s*64 + ...]
    float4 x0a = X4[lane];            float4 x0b = X4[32 + lane];
    float4 x1a = X4[64 + lane];       float4 x1b = X4[96 + lane];

    for (int s = 0; s < T_STEPS; s++) {
        const int buf = s & 1;
        const unsigned tau = ((unsigned)s >> 1) & 1u;
        const unsigned* hp = g_hbuf[buf] + 4 * t;

        // ---- Staggered poll: keep 3 rotating loads of the same line in
        // flight. Any returned copy whose 4 LSBs match tau is valid (monotone
        // location). Detect granularity ~= rotate cost, not one L2 RTT. ----
        uint4 va = ldv4(hp);
        uint4 vb = ldv4(hp);
        uint4 vc = ldv4(hp);

        // Prefetch x for step s+2 (two step-periods of DRAM cover).
        float4 x2a, x2b;
        x2a.x = x2a.y = x2a.z = x2a.w = 0.f;
        x2b = x2a;
        if (s + 2 < T_STEPS) {
            x2a = X4[(s + 2) * 64 + lane];
            x2b = X4[(s + 2) * 64 + 32 + lane];
        }

        // Input projection for THIS step (both rows) while polls are in flight.
        float a0 = (lane == 0) ? bias0 : 0.0f;
        float a1 = 0.f, a2 = 0.f, a3 = 0.f;
        float b0 = (lane == 0) ? bias1 : 0.0f;
        float b1 = 0.f, b2 = 0.f, b3 = 0.f;
        a0 = fmaf(wi0[0], x0a.x, a0);  a1 = fmaf(wi0[1], x0a.y, a1);
        a2 = fmaf(wi0[2], x0a.z, a2);  a3 = fmaf(wi0[3], x0a.w, a3);
        a0 = fmaf(wi0[4], x0b.x, a0);  a1 = fmaf(wi0[5], x0b.y, a1);
        a2 = fmaf(wi0[6], x0b.z, a2);  a3 = fmaf(wi0[7], x0b.w, a3);
        b0 = fmaf(wi1[0], x0a.x, b0);  b1 = fmaf(wi1[1], x0a.y, b1);
        b2 = fmaf(wi1[2], x0a.z, b2);  b3 = fmaf(wi1[3], x0a.w, b3);
        b0 = fmaf(wi1[4], x0b.x, b0);  b1 = fmaf(wi1[5], x0b.y, b1);
        b2 = fmaf(wi1[6], x0b.z, b2);  b3 = fmaf(wi1[7], x0b.w, b3);

        // Rotate-spin: accept the oldest ready copy; re-issue one on miss.
        while (notready(va, tau)) {
            va = vb;
            vb = vc;
            vc = ldv4(hp);
        }

        // Deposit as one STS.128 (LSB noise stays in the value; absorbed).
        *(uint4*)&sh[buf][4 * t] = va;

        __syncthreads();   // the only barrier per step

        // ---- Recurrent GEMV: 8x LDS.128 feed BOTH rows (64 FMA). ----
        const float* hs = sh[buf];
        #pragma unroll
        for (int g = 0; g < 8; g++) {
            float4 h4 = *(const float4*)(hs + g * 128 + 4 * lane);
            a0 = fmaf(w0[4 * g + 0], h4.x, a0);
            a1 = fmaf(w0[4 * g + 1], h4.y, a1);
            a2 = fmaf(w0[4 * g + 2], h4.z, a2);
            a3 = fmaf(w0[4 * g + 3], h4.w, a3);
            b0 = fmaf(w1[4 * g + 0], h4.x, b0);
            b1 = fmaf(w1[4 * g + 1], h4.y, b1);
            b2 = fmaf(w1[4 * g + 2], h4.z, b2);
            b3 = fmaf(w1[4 * g + 3], h4.w, b3);
        }
        float accA = (a0 + a1) + (a2 + a3);
        float accB = (b0 + b1) + (b2 + b3);

        // Two interleaved butterflies (ILP; all lanes get both sums).
        #pragma unroll
        for (int off = 16; off > 0; off >>= 1) {
            accA += __shfl_xor_sync(0xffffffffu, accA, off);
            accB += __shfl_xor_sync(0xffffffffu, accB, off);
        }

        // Parallel publish: lane 0 -> row r0, lane 1 -> row r1 (coalesced).
        const unsigned ntau = (((unsigned)(s + 1)) >> 1) & 1u;
        if (lane < 2) {
            float hnew = tanh_fast(lane == 0 ? accA : accB);
            unsigned ub = (__float_as_uint(hnew) & ~1u) | ntau;
            stx32(&g_hbuf[buf ^ 1][r0 + lane], ub);
        }

        x0a = x1a; x0b = x1b;
        x1a = x2a; x1b = x2b;
    }

    // ---- Epilogue: CTA 0 computes logits + log_softmax on h_T ----
    if (blockIdx.x == 0) {
        const unsigned tauT = ((unsigned)T_STEPS >> 1) & 1u;   // buffer 0
        for (int j = t; j < HID; j += TPB) {
            unsigned vv;
            do {
                asm volatile("ld.volatile.global.u32 %0, [%1];"
                             : "=r"(vv) : "l"(&g_hbuf[0][j]));
            } while ((vv & 1u) != tauT);
            sh[0][j] = __uint_as_float(vv);
        }
        __syncthreads();

        int orow = t >> 3;      // 32 rows x 8 threads
        int sub  = t & 7;
        float acc = 0.0f;
        #pragma unroll 4
        for (int j = 0; j < HID / 8; j += 4) {
            int col = sub * (HID / 8) + j;
            float4 w4 = ((const float4*)Wo)[(orow * HID + col) >> 2];
            acc = fmaf(w4.x, sh[0][col + 0], acc);
            acc = fmaf(w4.y, sh[0][col + 1], acc);
            acc = fmaf(w4.z, sh[0][col + 2], acc);
            acc = fmaf(w4.w, sh[0][col + 3], acc);
        }
        acc += __shfl_down_sync(0xffffffffu, acc, 4);
        acc += __shfl_down_sync(0xffffffffu, acc, 2);
        acc += __shfl_down_sync(0xffffffffu, acc, 1);

        __shared__ float s_log[NLAB];
        if (sub == 0) s_log[orow] = acc + bo[orow];
        __syncthreads();

        if (t < NLAB) {
            float vl = s_log[t];
            float m = vl;
            #pragma unroll
            for (int off = 16; off > 0; off >>= 1)
                m = fmaxf(m, __shfl_xor_sync(0xffffffffu, m, off));
            float e = expf(vl - m);
            float ssum = e;
            #pragma unroll
            for (int off = 16; off > 0; off >>= 1)
                ssum += __shfl_xor_sync(0xffffffffu, ssum, off);
            out[t] = vl - m - logf(ssum);
        }
    }
}

extern "C" void kernel_launch(void* const* d_in, const int* in_sizes, int n_in,
                              void* d_out, int out_size) {
    const float* X  = (const float*)d_in[0];
    const float* Wi = (const float*)d_in[1];
    const float* bi = (const float*)d_in[2];
    const float* Wh = (const float*)d_in[3];
    const float* bh = (const float*)d_in[4];
    const float* Wo = (const float*)d_in[5];
    const float* bo = (const float*)d_in[6];
    float* out = (float*)d_out;

    rnn_reset_kernel<<<1, 256>>>();
    rnn_scan_kernel<<<NCTA, TPB>>>(X, Wi, bi, Wh, bh, Wo, bo, out);
}